// round 4
// baseline (speedup 1.0000x reference)
#include <cuda_runtime.h>
#include <cuda_bf16.h>
#include <cstdint>

// LengthRegulator: x[B,T,D] f32, duration[B,T] i32 -> out[B,MAXL,D] f32, mel_len[B]
// B=32, T=1024, D=384, MAXL=8192 (fixed by the problem).
// d_out is ONE flattened float32 buffer: [B*MAXL*D] expanded tensor, then [B]
// mel_len values stored AS FLOAT32 (the harness casts the tuple to a single
// output dtype).

#define BB   32
#define TT   1024
#define DD   384
#define MAXL 8192

// Scratch: inclusive cumsum of duration per batch. 32*1024*4 = 128 KB.
__device__ int g_csum[BB][TT];

// ---------------------------------------------------------------------------
// Kernel 1: per-batch inclusive scan of duration (one block per batch,
// 1024 threads, Hillis-Steele in shared). Writes mel_len as FLOAT32 values
// directly after the main float output tensor.
// ---------------------------------------------------------------------------
__global__ void lr_cumsum_kernel(const int* __restrict__ dur, float* __restrict__ mel_out)
{
    __shared__ int s[TT];
    const int b = blockIdx.x;
    const int t = threadIdx.x;

    s[t] = dur[b * TT + t];
    __syncthreads();

    for (int off = 1; off < TT; off <<= 1) {
        int add = (t >= off) ? s[t - off] : 0;
        __syncthreads();
        s[t] += add;
        __syncthreads();
    }

    g_csum[b][t] = s[t];
    if (t == TT - 1) {
        mel_out[b] = (float)s[t];   // mel_len as float32 (harness's flattened dtype)
    }
}

// ---------------------------------------------------------------------------
// Kernel 2: gather/expand. Block = 1024 threads = 32 warps; each warp owns one
// output frame (32 consecutive frames per block). csum for the block's batch
// staged once in shared (4 KB) and reused by all 32 warps. Each warp does one
// uniform binary search (searchsorted right), then copies one row of D=384
// floats as 96 float4 (3 per lane), or zero-fills past mel_len.
// ---------------------------------------------------------------------------
__global__ __launch_bounds__(1024) void lr_gather_kernel(const float* __restrict__ x,
                                                         float* __restrict__ out)
{
    __shared__ int sc[TT];

    const int warp = threadIdx.x >> 5;
    const int lane = threadIdx.x & 31;

    // 32 consecutive frames per block; frames of a batch are contiguous in grid.
    const int blocks_per_batch = MAXL / 32;         // 256
    const int b = blockIdx.x / blocks_per_batch;
    const int f = (blockIdx.x % blocks_per_batch) * 32 + warp;

    // Stage this batch's csum into shared (int4 loads: 256 threads cover 1024 ints).
    if (threadIdx.x < TT / 4) {
        reinterpret_cast<int4*>(sc)[threadIdx.x] =
            reinterpret_cast<const int4*>(g_csum[b])[threadIdx.x];
    }
    __syncthreads();

    const int mel = sc[TT - 1];

    float4* orow = reinterpret_cast<float4*>(out + ((size_t)b * MAXL + f) * DD);

    if (f >= mel) {
        const float4 z = make_float4(0.f, 0.f, 0.f, 0.f);
        #pragma unroll
        for (int i = lane; i < DD / 4; i += 32) {
            orow[i] = z;
        }
    } else {
        // searchsorted(csum, f, side='right'): first index with sc[idx] > f.
        // Uniform across the warp (same f), so no divergence; LDS broadcasts.
        unsigned lo = 0, hi = TT;
        while (lo < hi) {
            unsigned mid = (lo + hi) >> 1;
            if (sc[mid] <= f) lo = mid + 1; else hi = mid;
        }
        int idx = (int)lo;
        if (idx > TT - 1) idx = TT - 1;   // jnp.clip (unreachable for f<mel, kept for safety)

        const float4* xrow = reinterpret_cast<const float4*>(x + ((size_t)b * TT + idx) * DD);
        #pragma unroll
        for (int i = lane; i < DD / 4; i += 32) {
            orow[i] = xrow[i];
        }
    }
}

// ---------------------------------------------------------------------------
// kernel_launch
// d_in[0] = x (f32, B*T*D), d_in[1] = duration (i32, B*T), d_in[2] = max_len (i32, 1)
// d_out: single float32 buffer. [0, B*MAXL*D) = expanded tensor,
// [B*MAXL*D, B*MAXL*D + B) = mel_len cast to float32.
// ---------------------------------------------------------------------------
extern "C" void kernel_launch(void* const* d_in, const int* in_sizes, int n_in,
                              void* d_out, int out_size)
{
    const float* x   = (const float*)d_in[0];
    const int*   dur = (const int*)d_in[1];

    float* out = (float*)d_out;

    const long long main_elems = (long long)BB * MAXL * DD;   // 100,663,296
    float* mel_out = out + main_elems;

    lr_cumsum_kernel<<<BB, TT>>>(dur, mel_out);
    lr_gather_kernel<<<(BB * MAXL) / 32, 1024>>>(x, out);
}

// round 8
// speedup vs baseline: 1.0313x; 1.0313x over previous
#include <cuda_runtime.h>
#include <cuda_bf16.h>
#include <cstdint>

// LengthRegulator: x[B,T,D] f32, duration[B,T] i32 -> out[B,MAXL,D] f32, mel_len[B]
// B=32, T=1024, D=384, MAXL=8192 (fixed by the problem).
// d_out is ONE flattened float32 buffer: [B*MAXL*D] expanded tensor, then [B]
// mel_len values stored AS FLOAT32.

#define BB   32
#define TT   1024
#define DD   384
#define MAXL 8192

// Scratch: frame -> token index table, -1 for invalid (zero-fill) frames.
// 32*8192*4 = 1 MB; written once by prep, read (L2-resident) by gather.
__device__ int g_idx[BB][MAXL];

// ---------------------------------------------------------------------------
// Kernel 1 (prep): per-batch inclusive scan of duration (Hillis-Steele in
// shared, 1024 threads = one per token), then:
//   - scatter token id t into g_idx[b][csum[t-1] .. csum[t])
//   - fill g_idx[b][mel .. MAXL) with -1
//   - write mel_len as float32 after the main output tensor
// Total writes: 1 MB. Runs in a few microseconds.
// ---------------------------------------------------------------------------
__global__ __launch_bounds__(TT) void lr_prep_kernel(const int* __restrict__ dur,
                                                     float* __restrict__ mel_out)
{
    __shared__ int s[TT];
    const int b = blockIdx.x;
    const int t = threadIdx.x;

    s[t] = dur[b * TT + t];
    __syncthreads();

    for (int off = 1; off < TT; off <<= 1) {
        int add = (t >= off) ? s[t - off] : 0;
        __syncthreads();
        s[t] += add;
        __syncthreads();
    }

    const int end   = (s[t] < MAXL) ? s[t] : MAXL;
    const int start = (t == 0) ? 0 : ((s[t - 1] < MAXL) ? s[t - 1] : MAXL);
    const int mel   = s[TT - 1];

    // Scatter: frames [start, end) map to token t (searchsorted-right semantics:
    // idx = first i with csum[i] > f).
    for (int f = start; f < end; ++f) {
        g_idx[b][f] = t;
    }
    // Invalid tail -> sentinel.
    for (int f = mel + t; f < MAXL; f += TT) {
        g_idx[b][f] = -1;
    }

    if (t == TT - 1) {
        mel_out[b] = (float)mel;   // mel_len as float32 (flattened output dtype)
    }
}

// ---------------------------------------------------------------------------
// Kernel 2 (gather/stream): 256 threads = 8 warps, one warp per output frame.
// No shared memory, no barriers, no search: one uniform cached idx load,
// then 3x LDG.128 + 3x STG.128 per lane (row of 384 floats), or zero stores.
// ---------------------------------------------------------------------------
__global__ __launch_bounds__(256) void lr_gather_kernel(const float* __restrict__ x,
                                                        float* __restrict__ out)
{
    const int warp = threadIdx.x >> 5;
    const int lane = threadIdx.x & 31;

    const int gf = blockIdx.x * 8 + warp;      // global frame over B*MAXL
    const int b  = gf >> 13;                    // / MAXL
    const int f  = gf & (MAXL - 1);

    const int idx = __ldg(&g_idx[b][f]);        // uniform across warp -> 1 sector

    float4* orow = reinterpret_cast<float4*>(out + (size_t)gf * DD);

    if (idx < 0) {
        const float4 z = make_float4(0.f, 0.f, 0.f, 0.f);
        #pragma unroll
        for (int i = lane; i < DD / 4; i += 32) {
            orow[i] = z;
        }
    } else {
        const float4* xrow = reinterpret_cast<const float4*>(x + ((size_t)b * TT + idx) * DD);
        #pragma unroll
        for (int i = lane; i < DD / 4; i += 32) {
            orow[i] = xrow[i];
        }
    }
}

// ---------------------------------------------------------------------------
// kernel_launch
// d_in[0] = x (f32, B*T*D), d_in[1] = duration (i32, B*T), d_in[2] = max_len (i32, 1)
// d_out: single float32 buffer. [0, B*MAXL*D) = expanded tensor,
// [B*MAXL*D, +B) = mel_len cast to float32.
// ---------------------------------------------------------------------------
extern "C" void kernel_launch(void* const* d_in, const int* in_sizes, int n_in,
                              void* d_out, int out_size)
{
    const float* x   = (const float*)d_in[0];
    const int*   dur = (const int*)d_in[1];

    float* out = (float*)d_out;

    const long long main_elems = (long long)BB * MAXL * DD;   // 100,663,296
    float* mel_out = out + main_elems;

    lr_prep_kernel<<<BB, TT>>>(dur, mel_out);
    lr_gather_kernel<<<(BB * MAXL) / 8, 256>>>(x, out);
}

// round 9
// speedup vs baseline: 1.0559x; 1.0239x over previous
#include <cuda_runtime.h>
#include <cuda_bf16.h>
#include <cstdint>

// LengthRegulator: x[B,T,D] f32, duration[B,T] i32 -> out[B,MAXL,D] f32, mel_len[B]
// B=32, T=1024, D=384, MAXL=8192 (fixed by the problem).
// d_out is ONE flattened float32 buffer: [B*MAXL*D] expanded tensor, then [B]
// mel_len values stored AS FLOAT32.

#define BB   32
#define TT   1024
#define DD   384
#define MAXL 8192

// Scratch: frame -> token index table, -1 for invalid (zero-fill) frames.
// 32*8192*4 = 1 MB; written once by prep, read (L2-resident) by gather.
__device__ int g_idx[BB][MAXL];

// ---------------------------------------------------------------------------
// Kernel 1 (prep): per-batch inclusive scan of duration via warp shuffles
// (5 shfl steps per warp + scan of 32 warp-sums, only 2 block barriers),
// then:
//   - scatter token id t into g_idx[b][csum[t-1] .. csum[t])
//   - fill g_idx[b][mel .. MAXL) with -1
//   - write mel_len as float32 after the main output tensor
// ---------------------------------------------------------------------------
__global__ __launch_bounds__(TT) void lr_prep_kernel(const int* __restrict__ dur,
                                                     float* __restrict__ mel_out)
{
    __shared__ int warp_sum[TT / 32];          // 32 per-warp totals
    __shared__ int warp_off[TT / 32];          // exclusive offsets of each warp

    const int b    = blockIdx.x;
    const int t    = threadIdx.x;
    const int lane = t & 31;
    const int warp = t >> 5;

    int v = dur[b * TT + t];

    // Inclusive scan within the warp (Kogge-Stone via shfl_up).
    int scan = v;
    #pragma unroll
    for (int off = 1; off < 32; off <<= 1) {
        int n = __shfl_up_sync(0xffffffffu, scan, off);
        if (lane >= off) scan += n;
    }
    if (lane == 31) warp_sum[warp] = scan;
    __syncthreads();

    // Warp 0 scans the 32 warp totals (exclusive).
    if (warp == 0) {
        int ws = warp_sum[lane];
        int wscan = ws;
        #pragma unroll
        for (int off = 1; off < 32; off <<= 1) {
            int n = __shfl_up_sync(0xffffffffu, wscan, off);
            if (lane >= off) wscan += n;
        }
        warp_off[lane] = wscan - ws;           // exclusive prefix
    }
    __syncthreads();

    const int csum_t  = scan + warp_off[warp];       // inclusive csum[t]
    const int csum_tm = csum_t - v;                  // csum[t-1] (0 for t==0)

    // Batch total: csum of last element; last warp's lane 31 has it, but every
    // thread can compute it as warp_off[31] + warp_sum[31].
    const int mel = warp_off[TT / 32 - 1] + warp_sum[TT / 32 - 1];

    const int start = (csum_tm < MAXL) ? csum_tm : MAXL;
    const int end   = (csum_t  < MAXL) ? csum_t  : MAXL;

    // Scatter: frames [start, end) map to token t (searchsorted-right semantics).
    for (int f = start; f < end; ++f) {
        g_idx[b][f] = t;
    }
    // Invalid tail -> sentinel.
    for (int f = mel + t; f < MAXL; f += TT) {
        g_idx[b][f] = -1;
    }

    if (t == 0) {
        mel_out[b] = (float)mel;   // mel_len as float32 (flattened output dtype)
    }
}

// ---------------------------------------------------------------------------
// Kernel 2 (gather/stream): 256 threads = 8 warps, one warp per output frame.
// No shared memory, no barriers, no search: one uniform cached idx load,
// then 3x LDG.128 + 3x streaming STG.128 per lane. Stores use __stcs
// (evict-first) so the 402 MB write stream doesn't evict x (50 MB) from L2;
// consecutive frames re-reading the same token row then hit L2.
// ---------------------------------------------------------------------------
__global__ __launch_bounds__(256) void lr_gather_kernel(const float* __restrict__ x,
                                                        float* __restrict__ out)
{
    const int warp = threadIdx.x >> 5;
    const int lane = threadIdx.x & 31;

    const int gf = blockIdx.x * 8 + warp;      // global frame over B*MAXL
    const int b  = gf >> 13;                    // / MAXL
    const int f  = gf & (MAXL - 1);

    const int idx = __ldg(&g_idx[b][f]);        // uniform across warp -> 1 sector

    float4* orow = reinterpret_cast<float4*>(out + (size_t)gf * DD);

    if (idx < 0) {
        const float4 z = make_float4(0.f, 0.f, 0.f, 0.f);
        #pragma unroll
        for (int i = lane; i < DD / 4; i += 32) {
            __stcs(orow + i, z);
        }
    } else {
        const float4* xrow = reinterpret_cast<const float4*>(x + ((size_t)b * TT + idx) * DD);
        #pragma unroll
        for (int i = lane; i < DD / 4; i += 32) {
            __stcs(orow + i, __ldg(xrow + i));
        }
    }
}

// ---------------------------------------------------------------------------
// kernel_launch
// d_in[0] = x (f32, B*T*D), d_in[1] = duration (i32, B*T), d_in[2] = max_len (i32, 1)
// d_out: single float32 buffer. [0, B*MAXL*D) = expanded tensor,
// [B*MAXL*D, +B) = mel_len cast to float32.
// ---------------------------------------------------------------------------
extern "C" void kernel_launch(void* const* d_in, const int* in_sizes, int n_in,
                              void* d_out, int out_size)
{
    const float* x   = (const float*)d_in[0];
    const int*   dur = (const int*)d_in[1];

    float* out = (float*)d_out;

    const long long main_elems = (long long)BB * MAXL * DD;   // 100,663,296
    float* mel_out = out + main_elems;

    lr_prep_kernel<<<BB, TT>>>(dur, mel_out);
    lr_gather_kernel<<<(BB * MAXL) / 8, 256>>>(x, out);
}

// round 10
// speedup vs baseline: 1.0798x; 1.0226x over previous
#include <cuda_runtime.h>
#include <cuda_bf16.h>
#include <cstdint>

// LengthRegulator: x[B,T,D] f32, duration[B,T] i32 -> out[B,MAXL,D] f32, mel_len[B]
// B=32, T=1024, D=384, MAXL=8192 (fixed by the problem).
// d_out is ONE flattened float32 buffer: [B*MAXL*D] expanded tensor, then [B]
// mel_len values stored AS FLOAT32.

#define BB   32
#define TT   1024
#define DD   384
#define MAXL 8192
#define SEGB 8                      // segments per batch (prep parallelism)
#define SEGL (MAXL / SEGB)          // 1024 frames per segment

// Scratch: frame -> token index table, -1 for invalid (zero-fill) frames.
// 32*8192*4 = 1 MB; written once by prep, read (L2-resident) by gather.
__device__ int g_idx[BB][MAXL];

// ---------------------------------------------------------------------------
// Kernel 1 (prep): 256 blocks = 8 segments x 32 batches. Each block re-scans
// its batch's durations (warp-shuffle scan, 2 barriers) and writes only the
// g_idx entries falling inside its 1024-frame segment window:
//   - scatter token id t into [csum[t-1], csum[t]) ∩ segment
//   - fill [mel, MAXL) ∩ segment with -1 (exactly one store per thread)
//   - segment 0 writes mel_len as float32 after the main output tensor
// Redundant scan cost: 4 KB dur load + ~15 cyc of shuffles per block — trivial;
// buys 8x the blocks for latency hiding on the scattered 1 MB of idx writes.
// ---------------------------------------------------------------------------
__global__ __launch_bounds__(TT) void lr_prep_kernel(const int* __restrict__ dur,
                                                     float* __restrict__ mel_out)
{
    __shared__ int warp_sum[TT / 32];          // 32 per-warp totals
    __shared__ int warp_off[TT / 32];          // exclusive offsets of each warp

    const int b      = blockIdx.x / SEGB;
    const int seg    = blockIdx.x % SEGB;
    const int seg_lo = seg * SEGL;
    const int seg_hi = seg_lo + SEGL;

    const int t    = threadIdx.x;
    const int lane = t & 31;
    const int warp = t >> 5;

    int v = dur[b * TT + t];

    // Inclusive scan within the warp (Kogge-Stone via shfl_up).
    int scan = v;
    #pragma unroll
    for (int off = 1; off < 32; off <<= 1) {
        int n = __shfl_up_sync(0xffffffffu, scan, off);
        if (lane >= off) scan += n;
    }
    if (lane == 31) warp_sum[warp] = scan;
    __syncthreads();

    // Warp 0 scans the 32 warp totals (exclusive).
    if (warp == 0) {
        int ws = warp_sum[lane];
        int wscan = ws;
        #pragma unroll
        for (int off = 1; off < 32; off <<= 1) {
            int n = __shfl_up_sync(0xffffffffu, wscan, off);
            if (lane >= off) wscan += n;
        }
        warp_off[lane] = wscan - ws;           // exclusive prefix
    }
    __syncthreads();

    const int csum_t  = scan + warp_off[warp];       // inclusive csum[t]
    const int csum_tm = csum_t - v;                  // csum[t-1] (0 for t==0)
    const int mel     = warp_off[TT / 32 - 1] + warp_sum[TT / 32 - 1];

    // Scatter restricted to this segment's window.
    int s2 = (csum_tm > seg_lo) ? csum_tm : seg_lo;
    int e2 = (csum_t  < seg_hi) ? csum_t  : seg_hi;
    for (int f = s2; f < e2; ++f) {
        g_idx[b][f] = t;                       // searchsorted-right: first i with csum[i] > f
    }

    // Invalid tail within this segment: one predicated store per thread.
    {
        int lo = (mel > seg_lo) ? mel : seg_lo;
        int f  = lo + t;
        if (f < seg_hi) {
            g_idx[b][f] = -1;
        }
    }

    if (seg == 0 && t == 0) {
        mel_out[b] = (float)mel;               // mel_len as float32 (flattened dtype)
    }
}

// ---------------------------------------------------------------------------
// Kernel 2 (gather/stream): 256 threads = 8 warps, one warp per output frame.
// No shared memory, no barriers, no search: one uniform cached idx load,
// then 3x LDG.128 + 3x streaming STG.128 per lane (row of 384 floats), or
// zero stores. Measured at the write-bandwidth plateau (~5.74 TB/s DRAM,
// reads ~fully L2-served) — do not touch.
// ---------------------------------------------------------------------------
__global__ __launch_bounds__(256) void lr_gather_kernel(const float* __restrict__ x,
                                                        float* __restrict__ out)
{
    const int warp = threadIdx.x >> 5;
    const int lane = threadIdx.x & 31;

    const int gf = blockIdx.x * 8 + warp;      // global frame over B*MAXL
    const int b  = gf >> 13;                    // / MAXL
    const int f  = gf & (MAXL - 1);

    const int idx = __ldg(&g_idx[b][f]);        // uniform across warp -> 1 sector

    float4* orow = reinterpret_cast<float4*>(out + (size_t)gf * DD);

    if (idx < 0) {
        const float4 z = make_float4(0.f, 0.f, 0.f, 0.f);
        #pragma unroll
        for (int i = lane; i < DD / 4; i += 32) {
            __stcs(orow + i, z);
        }
    } else {
        const float4* xrow = reinterpret_cast<const float4*>(x + ((size_t)b * TT + idx) * DD);
        #pragma unroll
        for (int i = lane; i < DD / 4; i += 32) {
            __stcs(orow + i, __ldg(xrow + i));
        }
    }
}

// ---------------------------------------------------------------------------
// kernel_launch
// d_in[0] = x (f32, B*T*D), d_in[1] = duration (i32, B*T), d_in[2] = max_len (i32, 1)
// d_out: single float32 buffer. [0, B*MAXL*D) = expanded tensor,
// [B*MAXL*D, +B) = mel_len cast to float32.
// ---------------------------------------------------------------------------
extern "C" void kernel_launch(void* const* d_in, const int* in_sizes, int n_in,
                              void* d_out, int out_size)
{
    const float* x   = (const float*)d_in[0];
    const int*   dur = (const int*)d_in[1];

    float* out = (float*)d_out;

    const long long main_elems = (long long)BB * MAXL * DD;   // 100,663,296
    float* mel_out = out + main_elems;

    lr_prep_kernel<<<BB * SEGB, TT>>>(dur, mel_out);
    lr_gather_kernel<<<(BB * MAXL) / 8, 256>>>(x, out);
}

// round 13
// speedup vs baseline: 1.0803x; 1.0004x over previous
#include <cuda_runtime.h>
#include <cuda_bf16.h>
#include <cstdint>

// LengthRegulator: x[B,T,D] f32, duration[B,T] i32 -> out[B,MAXL,D] f32, mel_len[B]
// B=32, T=1024, D=384, MAXL=8192 (fixed by the problem).
// d_out is ONE flattened float32 buffer: [B*MAXL*D] expanded tensor, then [B]
// mel_len values stored AS FLOAT32.

#define BB   32
#define TT   1024
#define DD   384
#define MAXL 8192
#define SEGB 8                      // segments per batch (prep parallelism)
#define SEGL (MAXL / SEGB)          // 1024 frames per segment

// Scratch: frame -> token index table, -1 for invalid (zero-fill) frames.
// 32*8192*4 = 1 MB; written once by prep, read (L2-resident) by gather.
__device__ int g_idx[BB][MAXL];

// ---------------------------------------------------------------------------
// Kernel 1 (prep): 256 blocks = 8 segments x 32 batches. Each block re-scans
// its batch's durations (warp-shuffle scan, 2 barriers) and writes only the
// g_idx entries falling inside its 1024-frame segment window. Signals PDL
// completion (launch_dependents) after its stores so the gather kernel can
// ramp up concurrently.
// ---------------------------------------------------------------------------
__global__ __launch_bounds__(TT) void lr_prep_kernel(const int* __restrict__ dur,
                                                     float* __restrict__ mel_out)
{
    __shared__ int warp_sum[TT / 32];          // 32 per-warp totals
    __shared__ int warp_off[TT / 32];          // exclusive offsets of each warp

    const int b      = blockIdx.x / SEGB;
    const int seg    = blockIdx.x % SEGB;
    const int seg_lo = seg * SEGL;
    const int seg_hi = seg_lo + SEGL;

    const int t    = threadIdx.x;
    const int lane = t & 31;
    const int warp = t >> 5;

    int v = dur[b * TT + t];

    // Inclusive scan within the warp (Kogge-Stone via shfl_up).
    int scan = v;
    #pragma unroll
    for (int off = 1; off < 32; off <<= 1) {
        int n = __shfl_up_sync(0xffffffffu, scan, off);
        if (lane >= off) scan += n;
    }
    if (lane == 31) warp_sum[warp] = scan;
    __syncthreads();

    // Warp 0 scans the 32 warp totals (exclusive).
    if (warp == 0) {
        int ws = warp_sum[lane];
        int wscan = ws;
        #pragma unroll
        for (int off = 1; off < 32; off <<= 1) {
            int n = __shfl_up_sync(0xffffffffu, wscan, off);
            if (lane >= off) wscan += n;
        }
        warp_off[lane] = wscan - ws;           // exclusive prefix
    }
    __syncthreads();

    const int csum_t  = scan + warp_off[warp];       // inclusive csum[t]
    const int csum_tm = csum_t - v;                  // csum[t-1] (0 for t==0)
    const int mel     = warp_off[TT / 32 - 1] + warp_sum[TT / 32 - 1];

    // Scatter restricted to this segment's window.
    int s2 = (csum_tm > seg_lo) ? csum_tm : seg_lo;
    int e2 = (csum_t  < seg_hi) ? csum_t  : seg_hi;
    for (int f = s2; f < e2; ++f) {
        g_idx[b][f] = t;                       // searchsorted-right: first i with csum[i] > f
    }

    // Invalid tail within this segment: one predicated store per thread.
    {
        int lo = (mel > seg_lo) ? mel : seg_lo;
        int f  = lo + t;
        if (f < seg_hi) {
            g_idx[b][f] = -1;
        }
    }

    if (seg == 0 && t == 0) {
        mel_out[b] = (float)mel;               // mel_len as float32 (flattened dtype)
    }

    // PDL: allow the dependent (gather) grid to launch; its griddepcontrol.wait
    // orders all of this kernel's stores before any dependent load.
    asm volatile("griddepcontrol.launch_dependents;" ::: "memory");
}

// ---------------------------------------------------------------------------
// Kernel 2 (gather/stream): 256 threads = 8 warps, one warp per output frame.
// Launched with PDL: prologue/index math overlaps prep; griddepcontrol.wait
// before the first g_idx read. Then one uniform cached idx load + 3x LDG.128
// + 3x streaming STG.128 per lane. Measured at the write-bandwidth plateau
// (~5.72 TB/s DRAM, reads ~fully L2-served) — body unchanged.
// ---------------------------------------------------------------------------
__global__ __launch_bounds__(256) void lr_gather_kernel(const float* __restrict__ x,
                                                        float* __restrict__ out)
{
    const int warp = threadIdx.x >> 5;
    const int lane = threadIdx.x & 31;

    const int gf = blockIdx.x * 8 + warp;      // global frame over B*MAXL
    const int b  = gf >> 13;                    // / MAXL
    const int f  = gf & (MAXL - 1);

    float4* orow = reinterpret_cast<float4*>(out + (size_t)gf * DD);

    // Wait for prep's stores to be visible before reading the idx table.
    asm volatile("griddepcontrol.wait;" ::: "memory");

    const int idx = __ldg(&g_idx[b][f]);        // uniform across warp -> 1 sector

    if (idx < 0) {
        const float4 z = make_float4(0.f, 0.f, 0.f, 0.f);
        #pragma unroll
        for (int i = lane; i < DD / 4; i += 32) {
            __stcs(orow + i, z);
        }
    } else {
        const float4* xrow = reinterpret_cast<const float4*>(x + ((size_t)b * TT + idx) * DD);
        #pragma unroll
        for (int i = lane; i < DD / 4; i += 32) {
            __stcs(orow + i, __ldg(xrow + i));
        }
    }
}

// ---------------------------------------------------------------------------
// kernel_launch
// d_in[0] = x (f32, B*T*D), d_in[1] = duration (i32, B*T), d_in[2] = max_len (i32, 1)
// d_out: single float32 buffer. [0, B*MAXL*D) = expanded tensor,
// [B*MAXL*D, +B) = mel_len cast to float32.
// Gather is launched with programmatic dependent launch so its ramp-up
// overlaps prep execution.
// ---------------------------------------------------------------------------
extern "C" void kernel_launch(void* const* d_in, const int* in_sizes, int n_in,
                              void* d_out, int out_size)
{
    const float* x   = (const float*)d_in[0];
    const int*   dur = (const int*)d_in[1];

    float* out = (float*)d_out;

    const long long main_elems = (long long)BB * MAXL * DD;   // 100,663,296
    float* mel_out = out + main_elems;

    lr_prep_kernel<<<BB * SEGB, TT>>>(dur, mel_out);

    cudaLaunchConfig_t cfg = {};
    cfg.gridDim  = dim3((BB * MAXL) / 8);
    cfg.blockDim = dim3(256);
    cfg.stream   = 0;
    cudaLaunchAttribute attrs[1];
    attrs[0].id = cudaLaunchAttributeProgrammaticStreamSerialization;
    attrs[0].val.programmaticStreamSerializationAllowed = 1;
    cfg.attrs    = attrs;
    cfg.numAttrs = 1;
    cudaLaunchKernelEx(&cfg, lr_gather_kernel, x, out);
}